// round 6
// baseline (speedup 1.0000x reference)
#include <cuda_runtime.h>
#include <math_constants.h>

#define BB     8
#define NN     4096
#define CIN    128
#define EOUT   5
#define SEMOUT 13
#define KSEL   30
#define QCAP   12
#define TP     32
#define XPAD   36
#define WPAD   129
#define NSLICE 2
#define SLEN   (NN / NSLICE)
#define KQT    128            // threads per knn block (each owns 2 queries)
#define KQ2    256            // queries per knn block

#define FINF  __int_as_float(0x7f800000)
#define FNINF __int_as_float(0xff800000)

// ---------------- scratch (static __device__, no runtime alloc) ----------------
__device__ float  g_fsemT[BB * NN * CIN];            // 16MB [b][n][c]
__device__ float4 g_tA[BB * NN];                     // (e0,e1,e2,e3)
__device__ float2 g_tB[BB * NN];                     // (e4, r=||e||^2)
__device__ int    g_nn[BB * NN * KSEL];              // final neighbor indices
__device__ float  g_pd[BB * NN * NSLICE * KSEL];     // partial scores (s' = dot - r/2)
__device__ int    g_pi[BB * NN * NSLICE * KSEL];     // partial indices

// ================================================================
// Phase 1 (identical to R4 except table emission -> g_tA/g_tB)
// ================================================================
__global__ void __launch_bounds__(128, 4) phase1_kernel(
    const float* __restrict__ f_sem, const float* __restrict__ f_ins,
    const float* __restrict__ W_adapt, const float* __restrict__ b_adapt,
    const float* __restrict__ gamma, const float* __restrict__ beta,
    const float* __restrict__ W_ins, const float* __restrict__ b_ins,
    float* __restrict__ e_out)
{
    extern __shared__ float sm1[];
    float* Ws = sm1;                      // 32*129
    float* Xs = sm1 + 32 * WPAD;          // 128*36 (reused as Ys)
    float* Wi = Xs + 128 * XPAD;          // 5*128 + 8

    const int tid = threadIdx.x;
    const int blk = blockIdx.x;
    const int b   = blk >> 7;
    const int n0  = (blk & 127) * TP;

    for (int i = tid; i < EOUT * 128; i += 128) Wi[i] = W_ins[i];
    if (tid < EOUT) Wi[EOUT * 128 + tid] = b_ins[tid];

    const float* fs = f_sem + ((size_t)b * CIN) * NN + n0;
    for (int i = tid; i < 128 * TP; i += 128) {
        int c = i >> 5, p = i & 31;
        Xs[c * XPAD + p] = fs[(size_t)c * NN + p];
    }
    __syncthreads();

    {
        float* dst = g_fsemT + ((size_t)(b * NN + n0)) * CIN + tid;
        #pragma unroll 4
        for (int p = 0; p < TP; p++)
            dst[(size_t)p * CIN] = Xs[tid * XPAD + p];
    }

    float acc[TP];
    #pragma unroll
    for (int p = 0; p < TP; p++) acc[p] = 0.f;

    #pragma unroll 1
    for (int ch = 0; ch < 4; ch++) {
        if (ch) __syncthreads();
        for (int i = tid; i < 32 * 128; i += 128) {
            int o  = i >> 5;
            int cc = i & 31;
            Ws[cc * WPAD + o] = W_adapt[o * 128 + ch * 32 + cc];
        }
        __syncthreads();

        #pragma unroll 4
        for (int cc = 0; cc < 32; cc++) {
            float w = Ws[cc * WPAD + tid];
            const float4* xr = (const float4*)(Xs + (ch * 32 + cc) * XPAD);
            #pragma unroll
            for (int p4 = 0; p4 < TP / 4; p4++) {
                float4 x = xr[p4];
                acc[4 * p4 + 0] = fmaf(w, x.x, acc[4 * p4 + 0]);
                acc[4 * p4 + 1] = fmaf(w, x.y, acc[4 * p4 + 1]);
                acc[4 * p4 + 2] = fmaf(w, x.z, acc[4 * p4 + 2]);
                acc[4 * p4 + 3] = fmaf(w, x.w, acc[4 * p4 + 3]);
            }
        }
    }

    const float g  = gamma[tid];
    const float bb = fmaf(g, b_adapt[tid], beta[tid]);
    const float* fi = f_ins + ((size_t)(b * CIN + tid)) * NN + n0;
    float y[TP];
    #pragma unroll
    for (int p = 0; p < TP; p++) {
        float a = fmaxf(fmaf(g, acc[p], bb), 0.f);
        y[p] = fi[p] + a;
    }
    __syncthreads();
    #pragma unroll
    for (int p = 0; p < TP; p++) Xs[tid * XPAD + p] = y[p];
    __syncthreads();

    if (tid < TP) {
        const int p = tid;
        float e[EOUT];
        #pragma unroll
        for (int j = 0; j < EOUT; j++) e[j] = Wi[EOUT * 128 + j];
        #pragma unroll 4
        for (int c = 0; c < 128; c++) {
            float x = Xs[c * XPAD + p];
            #pragma unroll
            for (int j = 0; j < EOUT; j++) e[j] = fmaf(Wi[j * 128 + c], x, e[j]);
        }
        float r = 0.f;
        #pragma unroll
        for (int j = 0; j < EOUT; j++) r = fmaf(e[j], e[j], r);
        const int n = n0 + p;
        float* eo = e_out + (size_t)b * EOUT * NN + n;
        #pragma unroll
        for (int j = 0; j < EOUT; j++) eo[(size_t)j * NN] = e[j];
        g_tA[b * NN + n] = make_float4(e[0], e[1], e[2], e[3]);
        g_tB[b * NN + n] = make_float2(e[4], r);
    }
}

// ================================================================
// Phase 2a: partial top-30 (largest s' = dot - r/2) over one slice.
// 128 threads x 2 queries; window-4 batched uniform candidate loads.
// ================================================================
__device__ __forceinline__ void sift_min(float* hd, int* hi, int pos, float s, int id)
{
    // min-heap (root = smallest kept score). hd/hi offset by column; stride KQ2.
    while (true) {
        int l = 2 * pos + 1, r = l + 1;
        float lv = (l < KSEL) ? hd[l * KQ2] : FINF;
        float rv = (r < KSEL) ? hd[r * KQ2] : FINF;
        int   ch; float cv;
        if (lv <= rv) { ch = l; cv = lv; } else { ch = r; cv = rv; }
        if (cv >= s) break;
        hd[pos * KQ2] = cv; hi[pos * KQ2] = hi[ch * KQ2];
        pos = ch;
    }
    hd[pos * KQ2] = s; hi[pos * KQ2] = id;
}

__global__ void __launch_bounds__(KQT) knn_partial_kernel()
{
    extern __shared__ float smk[];
    float* hd = smk;                          // KSEL*KQ2
    int*   hi = (int*)(hd + KSEL * KQ2);      // KSEL*KQ2
    float* qs = (float*)(hi + KSEL * KQ2);    // QCAP*KQ2
    int*   qi = (int*)(qs + QCAP * KQ2);      // QCAP*KQ2

    const int tid  = threadIdx.x;
    const int b    = blockIdx.x >> 5;             // 32 blocks/batch (16 qblk * 2 sl)
    const int qblk = (blockIdx.x >> 1) & 15;
    const int sl   = blockIdx.x & 1;
    const int q0   = (qblk << 8) + tid;
    const int q1   = q0 + KQT;
    const int base = sl * SLEN;

    const ulonglong2* tA = (const ulonglong2*)(g_tA + b * NN);
    const unsigned long long* tB = (const unsigned long long*)(g_tB + b * NN);

    // pack queries
    float4 qa0 = g_tA[b * NN + q0]; float2 qb0 = g_tB[b * NN + q0];
    float4 qa1 = g_tA[b * NN + q1]; float2 qb1 = g_tB[b * NN + q1];
    unsigned long long P01, P23, PK, R01, R23, RK;
    asm("mov.b64 %0,{%1,%2};" : "=l"(P01) : "r"(__float_as_uint(qa0.x)), "r"(__float_as_uint(qa0.y)));
    asm("mov.b64 %0,{%1,%2};" : "=l"(P23) : "r"(__float_as_uint(qa0.z)), "r"(__float_as_uint(qa0.w)));
    asm("mov.b64 %0,{%1,%2};" : "=l"(PK)  : "r"(__float_as_uint(qb0.x)), "r"(__float_as_uint(-0.5f)));
    asm("mov.b64 %0,{%1,%2};" : "=l"(R01) : "r"(__float_as_uint(qa1.x)), "r"(__float_as_uint(qa1.y)));
    asm("mov.b64 %0,{%1,%2};" : "=l"(R23) : "r"(__float_as_uint(qa1.z)), "r"(__float_as_uint(qa1.w)));
    asm("mov.b64 %0,{%1,%2};" : "=l"(RK)  : "r"(__float_as_uint(qb1.x)), "r"(__float_as_uint(-0.5f)));

    float* hd0 = hd + tid;        int* hi0 = hi + tid;
    float* hd1 = hd + tid + KQT;  int* hi1 = hi + tid + KQT;
    float* qs0 = qs + tid;        int* qi0 = qi + tid;
    float* qs1 = qs + tid + KQT;  int* qi1 = qi + tid + KQT;

    #pragma unroll
    for (int j = 0; j < KSEL; j++) {
        hd0[j * KQ2] = FNINF; hi0[j * KQ2] = 0;
        hd1[j * KQ2] = FNINF; hi1[j * KQ2] = 0;
    }

    float tau0 = FNINF, tau1 = FNINF;
    int   cnt0 = 0,     cnt1 = 0;

    #pragma unroll 1
    for (int m = base; m < base + SLEN; m += 4) {
        ulonglong2 A[4]; unsigned long long Bv[4];
        #pragma unroll
        for (int j = 0; j < 4; j++) { A[j] = tA[m + j]; Bv[j] = tB[m + j]; }

        #pragma unroll
        for (int j = 0; j < 4; j++) {
            unsigned long long a0, a1;
            asm("mul.rn.f32x2 %0,%1,%2;"    : "=l"(a0) : "l"(A[j].x), "l"(P01));
            asm("fma.rn.f32x2 %0,%1,%2,%3;" : "=l"(a0) : "l"(A[j].y), "l"(P23), "l"(a0));
            asm("fma.rn.f32x2 %0,%1,%2,%3;" : "=l"(a0) : "l"(Bv[j]),  "l"(PK),  "l"(a0));
            asm("mul.rn.f32x2 %0,%1,%2;"    : "=l"(a1) : "l"(A[j].x), "l"(R01));
            asm("fma.rn.f32x2 %0,%1,%2,%3;" : "=l"(a1) : "l"(A[j].y), "l"(R23), "l"(a1));
            asm("fma.rn.f32x2 %0,%1,%2,%3;" : "=l"(a1) : "l"(Bv[j]),  "l"(RK),  "l"(a1));
            float s0 = __uint_as_float((unsigned)a0) + __uint_as_float((unsigned)(a0 >> 32));
            float s1 = __uint_as_float((unsigned)a1) + __uint_as_float((unsigned)(a1 >> 32));
            if (s0 > tau0) { qs0[cnt0 * KQ2] = s0; qi0[cnt0 * KQ2] = m + j; cnt0++; }
            if (s1 > tau1) { qs1[cnt1 * KQ2] = s1; qi1[cnt1 * KQ2] = m + j; cnt1++; }
        }

        if (__any_sync(0xffffffffu, (cnt0 | cnt1) > 8)) {
            for (int j = 0; j < cnt0; j++) {
                float v = qs0[j * KQ2];
                if (v > hd0[0]) sift_min(hd0, hi0, 0, v, qi0[j * KQ2]);
            }
            for (int j = 0; j < cnt1; j++) {
                float v = qs1[j * KQ2];
                if (v > hd1[0]) sift_min(hd1, hi1, 0, v, qi1[j * KQ2]);
            }
            cnt0 = 0; cnt1 = 0;
            tau0 = hd0[0]; tau1 = hd1[0];
        }
    }
    for (int j = 0; j < cnt0; j++) {
        float v = qs0[j * KQ2];
        if (v > hd0[0]) sift_min(hd0, hi0, 0, v, qi0[j * KQ2]);
    }
    for (int j = 0; j < cnt1; j++) {
        float v = qs1[j * KQ2];
        if (v > hd1[0]) sift_min(hd1, hi1, 0, v, qi1[j * KQ2]);
    }

    const size_t off0 = ((size_t)(b * NN + q0) * NSLICE + sl) * KSEL;
    const size_t off1 = ((size_t)(b * NN + q1) * NSLICE + sl) * KSEL;
    #pragma unroll
    for (int j = 0; j < KSEL; j++) {
        g_pd[off0 + j] = hd0[j * KQ2];  g_pi[off0 + j] = hi0[j * KQ2];
        g_pd[off1 + j] = hd1[j * KQ2];  g_pi[off1 + j] = hi1[j * KQ2];
    }
}

// ================================================================
// Phase 2b: merge 2x30 partials -> 30 LARGEST s' (tie: smaller index).
// ================================================================
__global__ void __launch_bounds__(256) knn_merge_kernel()
{
    const int wq   = (blockIdx.x << 3) + (threadIdx.x >> 5);
    const int lane = threadIdx.x & 31;

    const size_t off = (size_t)wq * (NSLICE * KSEL);
    float s0 = FNINF, s1 = FNINF;
    int   i0 = 0x7fffffff, i1 = 0x7fffffff;
    if (lane < KSEL) {
        s0 = g_pd[off + lane];         i0 = g_pi[off + lane];
        s1 = g_pd[off + KSEL + lane];  i1 = g_pi[off + KSEL + lane];
    }

    int r0 = 0, r1 = 0;
    #pragma unroll
    for (int j = 0; j < KSEL; j++) {
        float a  = __shfl_sync(0xffffffffu, s0, j);
        int   ai = __shfl_sync(0xffffffffu, i0, j);
        r0 += (a > s0) || (a == s0 && ai < i0);
        r1 += (a > s1) || (a == s1 && ai < i1);
        float c  = __shfl_sync(0xffffffffu, s1, j);
        int   ci = __shfl_sync(0xffffffffu, i1, j);
        r0 += (c > s0) || (c == s0 && ci < i0);
        r1 += (c > s1) || (c == s1 && ci < i1);
    }
    int* dst = g_nn + (size_t)wq * KSEL;
    if (lane < KSEL) {
        if (r0 < KSEL) dst[r0] = i0;
        if (r1 < KSEL) dst[r1] = i1;
    }
}

// ================================================================
// Phase 3: warp-per-query gather-max over 30 neighbors + 13x128 conv
// ================================================================
__global__ void __launch_bounds__(256) gather_kernel(
    const float* __restrict__ W_sem, const float* __restrict__ b_sem,
    float* __restrict__ p_out)
{
    const int warp = (blockIdx.x << 3) + (threadIdx.x >> 5);
    const int lane = threadIdx.x & 31;
    const int b = warp >> 12, n = warp & (NN - 1);

    const int* nnp = g_nn + (size_t)warp * KSEL;
    int myid = nnp[lane < KSEL ? lane : 0];

    const float* base = g_fsemT + ((size_t)b * NN) * CIN + (lane << 2);
    float4 vmax = make_float4(FNINF, FNINF, FNINF, FNINF);
    #pragma unroll 6
    for (int k = 0; k < KSEL; k++) {
        int j = __shfl_sync(0xffffffffu, myid, k);
        float4 v = *(const float4*)(base + (size_t)j * CIN);
        vmax.x = fmaxf(vmax.x, v.x);
        vmax.y = fmaxf(vmax.y, v.y);
        vmax.z = fmaxf(vmax.z, v.z);
        vmax.w = fmaxf(vmax.w, v.w);
    }

    float out[SEMOUT];
    #pragma unroll
    for (int o = 0; o < SEMOUT; o++) {
        float4 w = *(const float4*)(W_sem + o * CIN + (lane << 2));
        float a = w.x * vmax.x;
        a = fmaf(w.y, vmax.y, a);
        a = fmaf(w.z, vmax.z, a);
        a = fmaf(w.w, vmax.w, a);
        a += __shfl_xor_sync(0xffffffffu, a, 16);
        a += __shfl_xor_sync(0xffffffffu, a, 8);
        a += __shfl_xor_sync(0xffffffffu, a, 4);
        a += __shfl_xor_sync(0xffffffffu, a, 2);
        a += __shfl_xor_sync(0xffffffffu, a, 1);
        out[o] = a;
    }
    if (lane == 0) {
        float* dst = p_out + ((size_t)b * SEMOUT) * NN + n;
        #pragma unroll
        for (int o = 0; o < SEMOUT; o++)
            dst[(size_t)o * NN] = out[o] + b_sem[o];
    }
}

// ================================================================
extern "C" void kernel_launch(void* const* d_in, const int* in_sizes, int n_in,
                              void* d_out, int out_size)
{
    (void)in_sizes; (void)n_in; (void)out_size;
    const float* f_sem   = (const float*)d_in[0];
    const float* f_ins   = (const float*)d_in[1];
    const float* W_adapt = (const float*)d_in[2];
    const float* b_adapt = (const float*)d_in[3];
    const float* gamma   = (const float*)d_in[4];
    const float* beta    = (const float*)d_in[5];
    const float* W_ins   = (const float*)d_in[6];
    const float* b_ins   = (const float*)d_in[7];
    const float* W_sem   = (const float*)d_in[8];
    const float* b_sem   = (const float*)d_in[9];

    float* p_out = (float*)d_out;                       // [B,13,N]
    float* e_out = p_out + (size_t)BB * SEMOUT * NN;    // [B,5,N]

    const int smem1 = (32 * WPAD + 128 * XPAD + EOUT * 128 + 8) * 4;
    const int smem2 = (KSEL * KQ2 + QCAP * KQ2) * 8;    // 84KB

    cudaFuncSetAttribute(phase1_kernel,      cudaFuncAttributeMaxDynamicSharedMemorySize, smem1);
    cudaFuncSetAttribute(knn_partial_kernel, cudaFuncAttributeMaxDynamicSharedMemorySize, smem2);

    phase1_kernel<<<BB * (NN / TP), 128, smem1>>>(
        f_sem, f_ins, W_adapt, b_adapt, gamma, beta, W_ins, b_ins, e_out);
    knn_partial_kernel<<<BB * (NN / KQ2) * NSLICE, KQT, smem2>>>();
    knn_merge_kernel<<<(BB * NN) / 8, 256>>>();
    gather_kernel<<<(BB * NN) / 8, 256>>>(W_sem, b_sem, p_out);
}